// round 1
// baseline (speedup 1.0000x reference)
#include <cuda_runtime.h>
#include <cuda_bf16.h>
#include <cstdint>

// Problem constants
#define BB 64
#define TT 2048
#define MM 512
#define PP 512

// Device scratch (allocation-free rule: __device__ globals)
__device__ float g_dsp[BB * MM];                 // ds @ W_d + b_wd + b_ud   (B, M)
__device__ __nv_bfloat16 g_UT[MM * MM];          // U_d transposed to [n][k], bf16
__device__ float g_l[BB * TT];                   // logits before softmax

// ---------------------------------------------------------------------------
// Kernel 1: ds_proj[b][n] = sum_k concat(h,c)[b][k] * W_d[k][n] + b_wd[n] + b_ud[n]
// grid=64 (one per b), block=256 (each thread 2 cols)
// ---------------------------------------------------------------------------
__global__ void k_dsproj(const float* __restrict__ h, const float* __restrict__ c,
                         const float* __restrict__ W, const float* __restrict__ bwd,
                         const float* __restrict__ bud) {
    __shared__ float ds[2 * PP];
    int b = blockIdx.x;
    for (int i = threadIdx.x; i < PP; i += blockDim.x) {
        ds[i] = h[b * PP + i];
        ds[PP + i] = c[b * PP + i];
    }
    __syncthreads();
    int n0 = threadIdx.x;
    int n1 = threadIdx.x + 256;
    float a0 = 0.f, a1 = 0.f;
#pragma unroll 4
    for (int k = 0; k < 2 * PP; k++) {
        float d = ds[k];
        a0 = fmaf(d, W[k * MM + n0], a0);
        a1 = fmaf(d, W[k * MM + n1], a1);
    }
    g_dsp[b * MM + n0] = a0 + bwd[n0] + bud[n0];
    g_dsp[b * MM + n1] = a1 + bwd[n1] + bud[n1];
}

// ---------------------------------------------------------------------------
// Kernel 2: g_UT[n][k] = bf16(U[k][n]).  grid=(16,16), block=(32,8)
// ---------------------------------------------------------------------------
__global__ void k_transU(const float* __restrict__ U) {
    __shared__ float tile[32][33];
    int n0 = blockIdx.x * 32, k0 = blockIdx.y * 32;
    for (int i = threadIdx.y; i < 32; i += 8)
        tile[i][threadIdx.x] = U[(k0 + i) * MM + n0 + threadIdx.x];
    __syncthreads();
    for (int i = threadIdx.y; i < 32; i += 8)
        g_UT[(n0 + i) * MM + (k0 + threadIdx.x)] = __float2bfloat16(tile[threadIdx.x][i]);
}

// ---------------------------------------------------------------------------
// Fast accurate tanh: 2 MUFU + few ALU, abs err ~1e-6
// ---------------------------------------------------------------------------
__device__ __forceinline__ float fast_tanh(float x) {
    float ax = fabsf(x);
    float e = __expf(2.0f * ax);                  // saturates to +inf safely
    float r = 1.0f - __fdividef(2.0f, e + 1.0f);
    return copysignf(r, x);
}

// ---------------------------------------------------------------------------
// Kernel 3: fused  l[b][t] = sum_n v[n] * tanh(dsp[b][n] + enc[b][t][:] @ U[:][n])
// CTA: 128 t-rows of one b. A tile (128x512 bf16, swizzled) resident in SMEM.
// N processed in 8 chunks of 64 (B tile 64x512 bf16).  8 warps, warp = m16 slab.
// mma.sync.aligned.m16n8k16.row.col.f32.bf16.bf16.f32
// ---------------------------------------------------------------------------
#define SMEM_A_BYTES (128 * 1024)     // 128 rows * 512 bf16
#define SMEM_B_BYTES (64 * 1024)      // 64 rows * 512 bf16
#define SMEM_TOTAL   (SMEM_A_BYTES + SMEM_B_BYTES + 2048 + 2048)

__global__ __launch_bounds__(256, 1) void k_main(const float* __restrict__ enc,
                                                 const float* __restrict__ vd) {
    extern __shared__ char smraw[];
    char* As = smraw;
    char* Bs = smraw + SMEM_A_BYTES;
    float* dsp_s = (float*)(smraw + SMEM_A_BYTES + SMEM_B_BYTES);
    float* v_s = dsp_s + MM;

    int blk = blockIdx.x;
    int b = blk >> 4;               // 16 t-tiles per batch
    int t0 = (blk & 15) << 7;
    int tid = threadIdx.x;
    int lane = tid & 31;
    int wid = tid >> 5;

    uint32_t sA = (uint32_t)__cvta_generic_to_shared(As);
    uint32_t sB = (uint32_t)__cvta_generic_to_shared(Bs);

    // ---- Load A tile: 128 rows x 512 fp32 -> bf16, 16B-chunk XOR swizzle ----
    const float4* src = (const float4*)(enc + (size_t)(b * TT + t0) * MM);
#pragma unroll 4
    for (int i = tid; i < 128 * 128; i += 256) {   // 16384 float4s
        int r = i >> 7;
        int kq = i & 127;                          // float4 index within row
        float4 f = src[i];
        __nv_bfloat162 lo2 = __floats2bfloat162_rn(f.x, f.y);
        __nv_bfloat162 hi2 = __floats2bfloat162_rn(f.z, f.w);
        uint2 u;
        u.x = reinterpret_cast<uint32_t&>(lo2);
        u.y = reinterpret_cast<uint32_t&>(hi2);
        int c = kq >> 1;                           // 16B chunk index (0..63)
        *(uint2*)(As + r * 1024 + ((c ^ (r & 7)) << 4) + ((kq & 1) << 3)) = u;
    }
    for (int i = tid; i < MM; i += 256) {
        dsp_s[i] = g_dsp[b * MM + i];
        v_s[i] = vd[i];
    }

    int m0 = wid << 4;              // warp's 16-row slab
    int g = lane >> 2;
    int tig = lane & 3;
    float lp0 = 0.f, lp1 = 0.f;     // logit partials for rows m0+g, m0+g+8

    for (int nc = 0; nc < 8; nc++) {
        __syncthreads();            // Bs free (prev mma done); A/ds ready for nc=0
        int nb = nc << 6;
        // ---- Load B chunk: UT rows [nb, nb+64), bf16, swizzled ----
        for (int i = tid; i < 4096; i += 256) {    // 16B chunks: 64 rows x 64
            int r = i >> 6;
            int cc = i & 63;
            uint4 val = *(const uint4*)(g_UT + ((nb + r) << 9) + (cc << 3));
            *(uint4*)(Bs + r * 1024 + ((cc ^ (r & 7)) << 4)) = val;
        }
        __syncthreads();

        float acc[8][4];
#pragma unroll
        for (int j = 0; j < 8; j++)
#pragma unroll
            for (int q = 0; q < 4; q++) acc[j][q] = 0.f;

#pragma unroll 4
        for (int ks = 0; ks < 32; ks++) {
            uint32_t a0, a1, a2, a3;
            {
                int r = m0 + (lane & 15);
                int cch = (ks << 1) + (lane >> 4);
                uint32_t addr = sA + r * 1024 + ((cch ^ (r & 7)) << 4);
                asm volatile("ldmatrix.sync.aligned.m8n8.x4.shared.b16 {%0,%1,%2,%3}, [%4];"
                             : "=r"(a0), "=r"(a1), "=r"(a2), "=r"(a3) : "r"(addr));
            }
#pragma unroll
            for (int j = 0; j < 8; j++) {
                int n = (j << 3) + (lane & 7);
                int cch = (ks << 1) + ((lane >> 3) & 1);
                uint32_t addr = sB + n * 1024 + ((cch ^ (n & 7)) << 4);
                uint32_t b0, b1;
                asm volatile("ldmatrix.sync.aligned.m8n8.x2.shared.b16 {%0,%1}, [%2];"
                             : "=r"(b0), "=r"(b1) : "r"(addr));
                asm volatile("mma.sync.aligned.m16n8k16.row.col.f32.bf16.bf16.f32 "
                             "{%0,%1,%2,%3}, {%4,%5,%6,%7}, {%8,%9}, {%0,%1,%2,%3};"
                             : "+f"(acc[j][0]), "+f"(acc[j][1]), "+f"(acc[j][2]), "+f"(acc[j][3])
                             : "r"(a0), "r"(a1), "r"(a2), "r"(a3), "r"(b0), "r"(b1));
            }
        }

        // ---- Epilogue for this n-chunk: tanh(acc + dsp) * v, accumulate ----
#pragma unroll
        for (int j = 0; j < 8; j++) {
            int cb = nb + (j << 3) + (tig << 1);
            float vv0 = v_s[cb], vv1 = v_s[cb + 1];
            float dd0 = dsp_s[cb], dd1 = dsp_s[cb + 1];
            lp0 += vv0 * fast_tanh(acc[j][0] + dd0) + vv1 * fast_tanh(acc[j][1] + dd1);
            lp1 += vv0 * fast_tanh(acc[j][2] + dd0) + vv1 * fast_tanh(acc[j][3] + dd1);
        }
    }

    // Reduce across the 4 lanes of each quad (different cols, same row)
    lp0 += __shfl_xor_sync(0xffffffffu, lp0, 1);
    lp0 += __shfl_xor_sync(0xffffffffu, lp0, 2);
    lp1 += __shfl_xor_sync(0xffffffffu, lp1, 1);
    lp1 += __shfl_xor_sync(0xffffffffu, lp1, 2);
    if (tig == 0) {
        g_l[b * TT + t0 + m0 + g] = lp0;
        g_l[b * TT + t0 + m0 + g + 8] = lp1;
    }
}

// ---------------------------------------------------------------------------
// Kernel 4: softmax over T per batch. grid=64, block=256, 8 vals/thread.
// ---------------------------------------------------------------------------
__global__ void k_softmax(float* __restrict__ out) {
    __shared__ float red[8];
    int b = blockIdx.x, tid = threadIdx.x, lane = tid & 31, wid = tid >> 5;
    float vals[8];
    float m = -1e30f;
#pragma unroll
    for (int i = 0; i < 8; i++) {
        vals[i] = g_l[b * TT + i * 256 + tid];
        m = fmaxf(m, vals[i]);
    }
#pragma unroll
    for (int o = 16; o; o >>= 1) m = fmaxf(m, __shfl_xor_sync(0xffffffffu, m, o));
    if (lane == 0) red[wid] = m;
    __syncthreads();
    m = red[0];
#pragma unroll
    for (int i = 1; i < 8; i++) m = fmaxf(m, red[i]);
    __syncthreads();

    float s = 0.f;
#pragma unroll
    for (int i = 0; i < 8; i++) {
        vals[i] = __expf(vals[i] - m);
        s += vals[i];
    }
#pragma unroll
    for (int o = 16; o; o >>= 1) s += __shfl_xor_sync(0xffffffffu, s, o);
    if (lane == 0) red[wid] = s;
    __syncthreads();
    s = 0.f;
#pragma unroll
    for (int i = 0; i < 8; i++) s += red[i];
    float inv = 1.0f / s;
#pragma unroll
    for (int i = 0; i < 8; i++) out[b * TT + i * 256 + tid] = vals[i] * inv;
}

// ---------------------------------------------------------------------------
extern "C" void kernel_launch(void* const* d_in, const int* in_sizes, int n_in,
                              void* d_out, int out_size) {
    const float* h   = (const float*)d_in[0];   // (64,512)
    const float* c   = (const float*)d_in[1];   // (64,512)
    const float* enc = (const float*)d_in[2];   // (64,2048,512)
    const float* W   = (const float*)d_in[3];   // (1024,512)
    const float* bwd = (const float*)d_in[4];   // (512,)
    const float* U   = (const float*)d_in[5];   // (512,512)
    const float* bud = (const float*)d_in[6];   // (512,)
    const float* vd  = (const float*)d_in[7];   // (512,1)
    // d_in[8] = b_vd: constant shift, softmax-invariant -> unused
    float* out = (float*)d_out;                 // (64,2048,1)

    cudaFuncSetAttribute(k_main, cudaFuncAttributeMaxDynamicSharedMemorySize, SMEM_TOTAL);

    k_dsproj<<<BB, 256>>>(h, c, W, bwd, bud);
    k_transU<<<dim3(16, 16), dim3(32, 8)>>>(U);
    k_main<<<(BB * TT) / 128, 256, SMEM_TOTAL>>>(enc, vd);
    k_softmax<<<BB, 256>>>(out);
}

// round 3
// speedup vs baseline: 1.2655x; 1.2655x over previous
#include <cuda_runtime.h>
#include <cuda_bf16.h>
#include <cstdint>

#define BB 64
#define TT 2048
#define MM 512
#define PP 512

// Device scratch
__device__ float g_dsp[BB * MM];
__device__ __nv_bfloat16 g_UT[MM * MM];          // U_d^T [n][k], bf16
__device__ float g_l[BB * TT];

__device__ __forceinline__ float tanh_fast(float x) {
    float y;
    asm("tanh.approx.f32 %0, %1;" : "=f"(y) : "f"(x));
    return y;
}
__device__ __forceinline__ void cp_async16(uint32_t dst, const void* src) {
    asm volatile("cp.async.cg.shared.global [%0], [%1], 16;" :: "r"(dst), "l"(src) : "memory");
}
__device__ __forceinline__ void cp_commit() {
    asm volatile("cp.async.commit_group;" ::: "memory");
}
__device__ __forceinline__ void cp_wait_all() {
    asm volatile("cp.async.wait_group 0;" ::: "memory");
}

#define SWZ16(r, c) (((r) << 10) + (((c) ^ ((r) & 7)) << 4))

// ---------------------------------------------------------------------------
// Kernel 1: ds_proj = concat(h,c) @ W_d + b_wd + b_ud
// grid = 16 bgrp x 4 nblk; CTA: 4 batches x 128 cols, full K=1024.
// ---------------------------------------------------------------------------
__global__ void k_dsproj(const float* __restrict__ h, const float* __restrict__ c,
                         const float* __restrict__ W, const float* __restrict__ bwd,
                         const float* __restrict__ bud) {
    __shared__ float ds[4][2 * PP];
    int bgrp = blockIdx.x >> 2;
    int nblk = blockIdx.x & 3;
    int tid = threadIdx.x;
    for (int i = tid; i < 4 * PP; i += 256) {
        int j = i >> 9, k = i & 511;
        ds[j][k] = h[(bgrp * 4 + j) * PP + k];
        ds[j][PP + k] = c[(bgrp * 4 + j) * PP + k];
    }
    __syncthreads();
    int n = nblk * 128 + (tid & 127);
    int bp = tid >> 7;
    const float* d0 = ds[bp * 2];
    const float* d1 = ds[bp * 2 + 1];
    float a0 = 0.f, a1 = 0.f;
#pragma unroll 4
    for (int k = 0; k < 2 * PP; k++) {
        float w = W[k * MM + n];
        a0 = fmaf(w, d0[k], a0);
        a1 = fmaf(w, d1[k], a1);
    }
    float bias = bwd[n] + bud[n];
    g_dsp[(bgrp * 4 + bp * 2) * MM + n] = a0 + bias;
    g_dsp[(bgrp * 4 + bp * 2 + 1) * MM + n] = a1 + bias;
}

// ---------------------------------------------------------------------------
// Kernel 2: g_UT[n][k] = bf16(U[k][n])
// ---------------------------------------------------------------------------
__global__ void k_transU(const float* __restrict__ U) {
    __shared__ float tile[32][33];
    int n0 = blockIdx.x * 32, k0 = blockIdx.y * 32;
    for (int i = threadIdx.y; i < 32; i += 8)
        tile[i][threadIdx.x] = U[(k0 + i) * MM + n0 + threadIdx.x];
    __syncthreads();
    for (int i = threadIdx.y; i < 32; i += 8)
        g_UT[(n0 + i) * MM + (k0 + threadIdx.x)] = __float2bfloat16(tile[threadIdx.x][i]);
}

// ---------------------------------------------------------------------------
// Kernel 3: fused GEMM + tanh + v-dot via mma.sync (bf16, fp32 accum).
// CTA = 128 t-rows x N512 x K512. A (128x512 bf16) resident in SMEM.
// B = U^T streamed in 8 chunks of n64 via cp.async (single buffer; next chunk
// issued before the per-chunk tanh epilogue). Warp grid 4m x 2n:
// warp = m32 x n32 per chunk -> acc[2][4][4].
// ---------------------------------------------------------------------------
#define A_OFF    0
#define B_OFF    131072
#define DSP_OFF  196608
#define V_OFF    198656
#define PART_OFF 200704
#define SMEM_TOTAL 201280

__global__ __launch_bounds__(256, 1) void k_main(const float* __restrict__ enc,
                                                 const float* __restrict__ vd) {
    extern __shared__ char sm[];
    uint32_t sbase = (uint32_t)__cvta_generic_to_shared(sm);
    uint32_t sA = sbase + A_OFF;
    uint32_t sB = sbase + B_OFF;
    float* dsp_s = (float*)(sm + DSP_OFF);
    float* v_s = (float*)(sm + V_OFF);
    float* part = (float*)(sm + PART_OFF);

    int blk = blockIdx.x;
    int b = blk >> 4;
    int t0 = (blk & 15) << 7;
    int tid = threadIdx.x;
    int lane = tid & 31;
    int wid = tid >> 5;
    int wm = wid & 3;                // m-slab (32 rows)
    int wn = wid >> 2;               // n-half (32 cols within n64 chunk)
    int g = lane >> 2;
    int tig = lane & 3;

    const __nv_bfloat16* UT = &g_UT[0];

    // ---- Issue cp.async for B chunk 0 FIRST (overlaps A DRAM load) ----
    {
        const __nv_bfloat16* srcB = UT;   // chunk 0 rows 0..63
        for (int i = tid; i < 4096; i += 256) {
            int r = i >> 6, c = i & 63;
            cp_async16(sB + SWZ16(r, c), srcB + (r << 9) + (c << 3));
        }
        cp_commit();
    }

    // ---- Load A tile: 128 x 512 fp32 -> bf16, XOR-swizzled rows of 1024B ----
    {
        const float4* src = (const float4*)(enc + (size_t)(b * TT + t0) * MM);
#pragma unroll 4
        for (int i = tid; i < 8192; i += 256) {
            int r = i >> 6;
            int c = i & 63;
            float4 f0 = src[(r << 7) + (c << 1)];
            float4 f1 = src[(r << 7) + (c << 1) + 1];
            __nv_bfloat162 p0 = __floats2bfloat162_rn(f0.x, f0.y);
            __nv_bfloat162 p1 = __floats2bfloat162_rn(f0.z, f0.w);
            __nv_bfloat162 p2 = __floats2bfloat162_rn(f1.x, f1.y);
            __nv_bfloat162 p3 = __floats2bfloat162_rn(f1.z, f1.w);
            uint4 u;
            u.x = *(uint32_t*)&p0; u.y = *(uint32_t*)&p1;
            u.z = *(uint32_t*)&p2; u.w = *(uint32_t*)&p3;
            *(uint4*)(sm + A_OFF + SWZ16(r, c)) = u;
        }
        for (int i = tid; i < MM; i += 256) {
            dsp_s[i] = g_dsp[b * MM + i];
            v_s[i] = vd[i];
        }
    }

    float lp[4] = {0.f, 0.f, 0.f, 0.f};

    // Precompute ldmatrix lane-address components
    int aRow0 = (wm << 5) + (lane & 15);          // slab 0 row
    int aRow1 = aRow0 + 16;                        // slab 1 row
    int aCadd = (lane >> 4);                       // 0/1 -> k-lo/k-hi 16B chunk
    int bQuad = lane >> 3;                         // 0..3
    int bRowIn = lane & 7;
    int bCadd = bQuad & 1;
    int bBlkHalf = bQuad >> 1;                     // 0/1 -> n8 block j, j+1

    for (int nc = 0; nc < 8; nc++) {
        cp_wait_all();
        __syncthreads();                            // B(nc) ready; A ready (nc=0)

        float acc[2][4][4];
#pragma unroll
        for (int mi = 0; mi < 2; mi++)
#pragma unroll
            for (int j = 0; j < 4; j++)
#pragma unroll
                for (int q = 0; q < 4; q++) acc[mi][j][q] = 0.f;

#pragma unroll 4
        for (int ks = 0; ks < 32; ks++) {
            uint32_t a[2][4];
#pragma unroll
            for (int mi = 0; mi < 2; mi++) {
                int r = mi ? aRow1 : aRow0;
                uint32_t addr = sA + SWZ16(r, (ks << 1) + aCadd);
                asm volatile("ldmatrix.sync.aligned.m8n8.x4.shared.b16 {%0,%1,%2,%3}, [%4];"
                             : "=r"(a[mi][0]), "=r"(a[mi][1]), "=r"(a[mi][2]), "=r"(a[mi][3])
                             : "r"(addr));
            }
            uint32_t bf[2][4];                      // [jp][ {b0,b1 of block 2jp} , {b0,b1 of 2jp+1} ]
#pragma unroll
            for (int jp = 0; jp < 2; jp++) {
                int n = (wn << 5) + (jp << 4) + (bBlkHalf << 3) + bRowIn;
                uint32_t addr = sB + SWZ16(n, (ks << 1) + bCadd);
                asm volatile("ldmatrix.sync.aligned.m8n8.x4.shared.b16 {%0,%1,%2,%3}, [%4];"
                             : "=r"(bf[jp][0]), "=r"(bf[jp][1]), "=r"(bf[jp][2]), "=r"(bf[jp][3])
                             : "r"(addr));
            }
#pragma unroll
            for (int mi = 0; mi < 2; mi++)
#pragma unroll
                for (int jp = 0; jp < 2; jp++) {
                    asm volatile("mma.sync.aligned.m16n8k16.row.col.f32.bf16.bf16.f32 "
                        "{%0,%1,%2,%3}, {%4,%5,%6,%7}, {%8,%9}, {%0,%1,%2,%3};"
                        : "+f"(acc[mi][jp * 2][0]), "+f"(acc[mi][jp * 2][1]),
                          "+f"(acc[mi][jp * 2][2]), "+f"(acc[mi][jp * 2][3])
                        : "r"(a[mi][0]), "r"(a[mi][1]), "r"(a[mi][2]), "r"(a[mi][3]),
                          "r"(bf[jp][0]), "r"(bf[jp][1]));
                    asm volatile("mma.sync.aligned.m16n8k16.row.col.f32.bf16.bf16.f32 "
                        "{%0,%1,%2,%3}, {%4,%5,%6,%7}, {%8,%9}, {%0,%1,%2,%3};"
                        : "+f"(acc[mi][jp * 2 + 1][0]), "+f"(acc[mi][jp * 2 + 1][1]),
                          "+f"(acc[mi][jp * 2 + 1][2]), "+f"(acc[mi][jp * 2 + 1][3])
                        : "r"(a[mi][0]), "r"(a[mi][1]), "r"(a[mi][2]), "r"(a[mi][3]),
                          "r"(bf[jp][2]), "r"(bf[jp][3]));
                }
        }

        __syncthreads();                            // B(nc) fully consumed

        // ---- Prefetch B chunk nc+1 (overlaps epilogue below) ----
        if (nc < 7) {
            const __nv_bfloat16* srcB = UT + ((nc + 1) << 6) * MM;
            for (int i = tid; i < 4096; i += 256) {
                int r = i >> 6, c = i & 63;
                cp_async16(sB + SWZ16(r, c), srcB + (r << 9) + (c << 3));
            }
        }
        cp_commit();

        // ---- Epilogue for this chunk: tanh(acc + dsp) * v -> logit partials ----
        int nbase = (nc << 6) + (wn << 5) + (tig << 1);
#pragma unroll
        for (int mi = 0; mi < 2; mi++)
#pragma unroll
            for (int j = 0; j < 4; j++) {
                int cb = nbase + (j << 3);
                float v0 = v_s[cb], v1 = v_s[cb + 1];
                float d0 = dsp_s[cb], d1 = dsp_s[cb + 1];
                lp[mi * 2 + 0] += v0 * tanh_fast(acc[mi][j][0] + d0)
                                + v1 * tanh_fast(acc[mi][j][1] + d1);
                lp[mi * 2 + 1] += v0 * tanh_fast(acc[mi][j][2] + d0)
                                + v1 * tanh_fast(acc[mi][j][3] + d1);
            }
    }

    // ---- Reduce across quad lanes (cols) ----
#pragma unroll
    for (int q = 0; q < 4; q++) {
        lp[q] += __shfl_xor_sync(0xffffffffu, lp[q], 1);
        lp[q] += __shfl_xor_sync(0xffffffffu, lp[q], 2);
    }
    int row[4];
    row[0] = (wm << 5) + g;
    row[1] = (wm << 5) + 8 + g;
    row[2] = (wm << 5) + 16 + g;
    row[3] = (wm << 5) + 24 + g;
    if (wn == 1 && tig == 0) {
#pragma unroll
        for (int q = 0; q < 4; q++) part[row[q]] = lp[q];
    }
    __syncthreads();
    if (wn == 0 && tig == 0) {
#pragma unroll
        for (int q = 0; q < 4; q++)
            g_l[b * TT + t0 + row[q]] = lp[q] + part[row[q]];
    }
}

// ---------------------------------------------------------------------------
// Kernel 4: softmax over T per batch
// ---------------------------------------------------------------------------
__global__ void k_softmax(float* __restrict__ out) {
    __shared__ float red[8];
    int b = blockIdx.x, tid = threadIdx.x, lane = tid & 31, wid = tid >> 5;
    float vals[8];
    float m = -1e30f;
#pragma unroll
    for (int i = 0; i < 8; i++) {
        vals[i] = g_l[b * TT + i * 256 + tid];
        m = fmaxf(m, vals[i]);
    }
#pragma unroll
    for (int o = 16; o; o >>= 1) m = fmaxf(m, __shfl_xor_sync(0xffffffffu, m, o));
    if (lane == 0) red[wid] = m;
    __syncthreads();
    m = red[0];
#pragma unroll
    for (int i = 1; i < 8; i++) m = fmaxf(m, red[i]);
    __syncthreads();
    float s = 0.f;
#pragma unroll
    for (int i = 0; i < 8; i++) {
        vals[i] = __expf(vals[i] - m);
        s += vals[i];
    }
#pragma unroll
    for (int o = 16; o; o >>= 1) s += __shfl_xor_sync(0xffffffffu, s, o);
    if (lane == 0) red[wid] = s;
    __syncthreads();
    s = 0.f;
#pragma unroll
    for (int i = 0; i < 8; i++) s += red[i];
    float inv = 1.0f / s;
#pragma unroll
    for (int i = 0; i < 8; i++) out[b * TT + i * 256 + tid] = vals[i] * inv;
}

// ---------------------------------------------------------------------------
extern "C" void kernel_launch(void* const* d_in, const int* in_sizes, int n_in,
                              void* d_out, int out_size) {
    const float* h   = (const float*)d_in[0];
    const float* c   = (const float*)d_in[1];
    const float* enc = (const float*)d_in[2];
    const float* W   = (const float*)d_in[3];
    const float* bwd = (const float*)d_in[4];
    const float* U   = (const float*)d_in[5];
    const float* bud = (const float*)d_in[6];
    const float* vd  = (const float*)d_in[7];
    float* out = (float*)d_out;

    cudaFuncSetAttribute(k_main, cudaFuncAttributeMaxDynamicSharedMemorySize, SMEM_TOTAL);

    k_dsproj<<<64, 256>>>(h, c, W, bwd, bud);
    k_transU<<<dim3(16, 16), dim3(32, 8)>>>(U);
    k_main<<<(BB * TT) / 128, 256, SMEM_TOTAL>>>(enc, vd);
    k_softmax<<<BB, 256>>>(out);
}

// round 4
// speedup vs baseline: 1.2765x; 1.0087x over previous
#include <cuda_runtime.h>
#include <cuda_bf16.h>
#include <cstdint>

#define BB 64
#define TT 2048
#define MM 512
#define PP 512

// Device scratch
__device__ float g_dsp[BB * MM];
__device__ __nv_bfloat16 g_UT[MM * MM];          // U_d^T [n][k], bf16
__device__ float g_l[BB * TT];
__device__ int g_dummy;

__device__ __forceinline__ float tanh_fast(float x) {
    float y;
    asm("tanh.approx.f32 %0, %1;" : "=f"(y) : "f"(x));
    return y;
}
__device__ __forceinline__ void cp_async16(uint32_t dst, const void* src) {
    asm volatile("cp.async.cg.shared.global [%0], [%1], 16;" :: "r"(dst), "l"(src) : "memory");
}
__device__ __forceinline__ void cp_commit() {
    asm volatile("cp.async.commit_group;" ::: "memory");
}
__device__ __forceinline__ void cp_wait1() {
    asm volatile("cp.async.wait_group 1;" ::: "memory");
}

#define SWZ16(r, c) (((r) << 10) + (((c) ^ ((r) & 7)) << 4))

// ---------------------------------------------------------------------------
// Kernel 0: dummy (shifts ncu capture slot toward k_main)
// ---------------------------------------------------------------------------
__global__ void k_dummy() { if (threadIdx.x == 0) g_dummy = 1; }

// ---------------------------------------------------------------------------
// Kernel 1: ds_proj = concat(h,c) @ W_d + b_wd + b_ud
// ---------------------------------------------------------------------------
__global__ void k_dsproj(const float* __restrict__ h, const float* __restrict__ c,
                         const float* __restrict__ W, const float* __restrict__ bwd,
                         const float* __restrict__ bud) {
    __shared__ float ds[4][2 * PP];
    int bgrp = blockIdx.x >> 2;
    int nblk = blockIdx.x & 3;
    int tid = threadIdx.x;
    for (int i = tid; i < 4 * PP; i += 256) {
        int j = i >> 9, k = i & 511;
        ds[j][k] = h[(bgrp * 4 + j) * PP + k];
        ds[j][PP + k] = c[(bgrp * 4 + j) * PP + k];
    }
    __syncthreads();
    int n = nblk * 128 + (tid & 127);
    int bp = tid >> 7;
    const float* d0 = ds[bp * 2];
    const float* d1 = ds[bp * 2 + 1];
    float a0 = 0.f, a1 = 0.f;
#pragma unroll 4
    for (int k = 0; k < 2 * PP; k++) {
        float w = W[k * MM + n];
        a0 = fmaf(w, d0[k], a0);
        a1 = fmaf(w, d1[k], a1);
    }
    float bias = bwd[n] + bud[n];
    g_dsp[(bgrp * 4 + bp * 2) * MM + n] = a0 + bias;
    g_dsp[(bgrp * 4 + bp * 2 + 1) * MM + n] = a1 + bias;
}

// ---------------------------------------------------------------------------
// Kernel 2: g_UT[n][k] = bf16(U[k][n])
// ---------------------------------------------------------------------------
__global__ void k_transU(const float* __restrict__ U) {
    __shared__ float tile[32][33];
    int n0 = blockIdx.x * 32, k0 = blockIdx.y * 32;
    for (int i = threadIdx.y; i < 32; i += 8)
        tile[i][threadIdx.x] = U[(k0 + i) * MM + n0 + threadIdx.x];
    __syncthreads();
    for (int i = threadIdx.y; i < 32; i += 8)
        g_UT[(n0 + i) * MM + (k0 + threadIdx.x)] = __float2bfloat16(tile[threadIdx.x][i]);
}

// ---------------------------------------------------------------------------
// Kernel 3: fused GEMM + tanh + v-dot via mma.sync (bf16, fp32 accum).
// CTA = 128 t-rows x N512 x K512, A (128x512 bf16) resident in SMEM.
// B streamed in 8 n64-chunks; each chunk loaded as two k-half waves into
// DISJOINT halves of one 64KB buffer -> cp.async double-buffering with no
// extra smem. Inner ks loop double-buffers ldmatrix fragments.
// ---------------------------------------------------------------------------
#define A_OFF    0
#define B_OFF    131072
#define DSP_OFF  196608
#define V_OFF    198656
#define PART_OFF 200704
#define SMEM_TOTAL 201280

__global__ __launch_bounds__(256, 1) void k_main(const float* __restrict__ enc,
                                                 const float* __restrict__ vd) {
    extern __shared__ char sm[];
    uint32_t sbase = (uint32_t)__cvta_generic_to_shared(sm);
    uint32_t sA = sbase + A_OFF;
    uint32_t sB = sbase + B_OFF;
    float* dsp_s = (float*)(sm + DSP_OFF);
    float* v_s = (float*)(sm + V_OFF);
    float* part = (float*)(sm + PART_OFF);

    int blk = blockIdx.x;
    int b = blk >> 4;
    int t0 = (blk & 15) << 7;
    int tid = threadIdx.x;
    int lane = tid & 31;
    int wid = tid >> 5;
    int wm = wid & 3;
    int wn = wid >> 2;
    int g = lane >> 2;
    int tig = lane & 3;

    const __nv_bfloat16* UT = &g_UT[0];

    // ---- B half-chunk loader: chunk nc, k-half h (chunk cols h*32..h*32+31)
    auto loadBhalf = [&](int nc, int h) {
        const __nv_bfloat16* srcB = UT + (nc << 6) * MM;
        int cadd = h << 5;
#pragma unroll
        for (int i = tid; i < 2048; i += 256) {
            int r = i >> 5;
            int c = (i & 31) + cadd;
            cp_async16(sB + SWZ16(r, c), srcB + (r << 9) + (c << 3));
        }
    };

    // ---- Prologue: queue both k-halves of B chunk 0 (overlap with A load) ----
    loadBhalf(0, 0); cp_commit();
    loadBhalf(0, 1); cp_commit();

    // ---- Load A tile: 128 x 512 fp32 -> bf16, XOR-swizzled 1024B rows ----
    {
        const float4* src = (const float4*)(enc + (size_t)(b * TT + t0) * MM);
#pragma unroll 8
        for (int i = tid; i < 8192; i += 256) {
            int r = i >> 6;
            int c = i & 63;
            float4 f0 = src[(r << 7) + (c << 1)];
            float4 f1 = src[(r << 7) + (c << 1) + 1];
            __nv_bfloat162 p0 = __floats2bfloat162_rn(f0.x, f0.y);
            __nv_bfloat162 p1 = __floats2bfloat162_rn(f0.z, f0.w);
            __nv_bfloat162 p2 = __floats2bfloat162_rn(f1.x, f1.y);
            __nv_bfloat162 p3 = __floats2bfloat162_rn(f1.z, f1.w);
            uint4 u;
            u.x = *(uint32_t*)&p0; u.y = *(uint32_t*)&p1;
            u.z = *(uint32_t*)&p2; u.w = *(uint32_t*)&p3;
            *(uint4*)(sm + A_OFF + SWZ16(r, c)) = u;
        }
        for (int i = tid; i < MM; i += 256) {
            dsp_s[i] = g_dsp[b * MM + i];
            v_s[i] = vd[i];
        }
    }

    float lp[4] = {0.f, 0.f, 0.f, 0.f};

    // ldmatrix lane-address components
    int aRow0 = (wm << 5) + (lane & 15);
    int aRow1 = aRow0 + 16;
    int aCadd = (lane >> 4);
    int bQuad = lane >> 3;
    int bRowIn = lane & 7;
    int bCadd = bQuad & 1;
    int bBlkHalf = bQuad >> 1;
    int bN0 = (wn << 5) + (bBlkHalf << 3) + bRowIn;        // jp=0
    int bN1 = bN0 + 16;                                    // jp=1

    uint32_t af[2][2][4];   // [buf][mi][reg]
    uint32_t bfr[2][2][4];  // [buf][jp][reg]

    auto loadFrags = [&](int buf, int ks) {
#pragma unroll
        for (int mi = 0; mi < 2; mi++) {
            int r = mi ? aRow1 : aRow0;
            uint32_t addr = sA + SWZ16(r, (ks << 1) + aCadd);
            asm volatile("ldmatrix.sync.aligned.m8n8.x4.shared.b16 {%0,%1,%2,%3}, [%4];"
                         : "=r"(af[buf][mi][0]), "=r"(af[buf][mi][1]),
                           "=r"(af[buf][mi][2]), "=r"(af[buf][mi][3]) : "r"(addr));
        }
#pragma unroll
        for (int jp = 0; jp < 2; jp++) {
            int n = jp ? bN1 : bN0;
            uint32_t addr = sB + SWZ16(n, (ks << 1) + bCadd);
            asm volatile("ldmatrix.sync.aligned.m8n8.x4.shared.b16 {%0,%1,%2,%3}, [%4];"
                         : "=r"(bfr[buf][jp][0]), "=r"(bfr[buf][jp][1]),
                           "=r"(bfr[buf][jp][2]), "=r"(bfr[buf][jp][3]) : "r"(addr));
        }
    };

    float acc[2][4][4];

    for (int nc = 0; nc < 8; nc++) {
#pragma unroll
        for (int mi = 0; mi < 2; mi++)
#pragma unroll
            for (int j = 0; j < 4; j++)
#pragma unroll
                for (int q = 0; q < 4; q++) acc[mi][j][q] = 0.f;

#pragma unroll
        for (int h = 0; h < 2; h++) {
            cp_wait1();
            __syncthreads();                    // B half (nc,h) ready
            int kbase = h << 4;

            loadFrags(0, kbase);
#pragma unroll
            for (int kk = 0; kk < 16; kk++) {
                int cur = kk & 1;
                if (kk < 15) loadFrags(cur ^ 1, kbase + kk + 1);
#pragma unroll
                for (int mi = 0; mi < 2; mi++)
#pragma unroll
                    for (int jp = 0; jp < 2; jp++) {
                        asm volatile("mma.sync.aligned.m16n8k16.row.col.f32.bf16.bf16.f32 "
                            "{%0,%1,%2,%3}, {%4,%5,%6,%7}, {%8,%9}, {%0,%1,%2,%3};"
                            : "+f"(acc[mi][jp * 2][0]), "+f"(acc[mi][jp * 2][1]),
                              "+f"(acc[mi][jp * 2][2]), "+f"(acc[mi][jp * 2][3])
                            : "r"(af[cur][mi][0]), "r"(af[cur][mi][1]),
                              "r"(af[cur][mi][2]), "r"(af[cur][mi][3]),
                              "r"(bfr[cur][jp][0]), "r"(bfr[cur][jp][1]));
                        asm volatile("mma.sync.aligned.m16n8k16.row.col.f32.bf16.bf16.f32 "
                            "{%0,%1,%2,%3}, {%4,%5,%6,%7}, {%8,%9}, {%0,%1,%2,%3};"
                            : "+f"(acc[mi][jp * 2 + 1][0]), "+f"(acc[mi][jp * 2 + 1][1]),
                              "+f"(acc[mi][jp * 2 + 1][2]), "+f"(acc[mi][jp * 2 + 1][3])
                            : "r"(af[cur][mi][0]), "r"(af[cur][mi][1]),
                              "r"(af[cur][mi][2]), "r"(af[cur][mi][3]),
                              "r"(bfr[cur][jp][2]), "r"(bfr[cur][jp][3]));
                    }
            }
            __syncthreads();                    // all warps done reading half (nc,h)
            if (nc < 7) loadBhalf(nc + 1, h);
            cp_commit();
        }

        // ---- Epilogue for chunk nc ----
        int nbase = (nc << 6) + (wn << 5) + (tig << 1);
#pragma unroll
        for (int mi = 0; mi < 2; mi++)
#pragma unroll
            for (int j = 0; j < 4; j++) {
                int cb = nbase + (j << 3);
                float v0 = v_s[cb], v1 = v_s[cb + 1];
                float d0 = dsp_s[cb], d1 = dsp_s[cb + 1];
                lp[mi * 2 + 0] += v0 * tanh_fast(acc[mi][j][0] + d0)
                                + v1 * tanh_fast(acc[mi][j][1] + d1);
                lp[mi * 2 + 1] += v0 * tanh_fast(acc[mi][j][2] + d0)
                                + v1 * tanh_fast(acc[mi][j][3] + d1);
            }
    }

    // ---- Reduce across quad lanes (cols) ----
#pragma unroll
    for (int q = 0; q < 4; q++) {
        lp[q] += __shfl_xor_sync(0xffffffffu, lp[q], 1);
        lp[q] += __shfl_xor_sync(0xffffffffu, lp[q], 2);
    }
    int row[4];
    row[0] = (wm << 5) + g;
    row[1] = (wm << 5) + 8 + g;
    row[2] = (wm << 5) + 16 + g;
    row[3] = (wm << 5) + 24 + g;
    if (wn == 1 && tig == 0) {
#pragma unroll
        for (int q = 0; q < 4; q++) part[row[q]] = lp[q];
    }
    __syncthreads();
    if (wn == 0 && tig == 0) {
#pragma unroll
        for (int q = 0; q < 4; q++)
            g_l[b * TT + t0 + row[q]] = lp[q] + part[row[q]];
    }
}

// ---------------------------------------------------------------------------
// Kernel 4: softmax over T per batch
// ---------------------------------------------------------------------------
__global__ void k_softmax(float* __restrict__ out) {
    __shared__ float red[8];
    int b = blockIdx.x, tid = threadIdx.x, lane = tid & 31, wid = tid >> 5;
    float vals[8];
    float m = -1e30f;
#pragma unroll
    for (int i = 0; i < 8; i++) {
        vals[i] = g_l[b * TT + i * 256 + tid];
        m = fmaxf(m, vals[i]);
    }
#pragma unroll
    for (int o = 16; o; o >>= 1) m = fmaxf(m, __shfl_xor_sync(0xffffffffu, m, o));
    if (lane == 0) red[wid] = m;
    __syncthreads();
    m = red[0];
#pragma unroll
    for (int i = 1; i < 8; i++) m = fmaxf(m, red[i]);
    __syncthreads();
    float s = 0.f;
#pragma unroll
    for (int i = 0; i < 8; i++) {
        vals[i] = __expf(vals[i] - m);
        s += vals[i];
    }
#pragma unroll
    for (int o = 16; o; o >>= 1) s += __shfl_xor_sync(0xffffffffu, s, o);
    if (lane == 0) red[wid] = s;
    __syncthreads();
    s = 0.f;
#pragma unroll
    for (int i = 0; i < 8; i++) s += red[i];
    float inv = 1.0f / s;
#pragma unroll
    for (int i = 0; i < 8; i++) out[b * TT + i * 256 + tid] = vals[i] * inv;
}

// ---------------------------------------------------------------------------
extern "C" void kernel_launch(void* const* d_in, const int* in_sizes, int n_in,
                              void* d_out, int out_size) {
    const float* h   = (const float*)d_in[0];
    const float* c   = (const float*)d_in[1];
    const float* enc = (const float*)d_in[2];
    const float* W   = (const float*)d_in[3];
    const float* bwd = (const float*)d_in[4];
    const float* U   = (const float*)d_in[5];
    const float* bud = (const float*)d_in[6];
    const float* vd  = (const float*)d_in[7];
    float* out = (float*)d_out;

    cudaFuncSetAttribute(k_main, cudaFuncAttributeMaxDynamicSharedMemorySize, SMEM_TOTAL);

    k_dummy<<<1, 32>>>();
    k_dsproj<<<64, 256>>>(h, c, W, bwd, bud);
    k_transU<<<dim3(16, 16), dim3(32, 8)>>>(U);
    k_main<<<(BB * TT) / 128, 256, SMEM_TOTAL>>>(enc, vd);
    k_softmax<<<BB, 256>>>(out);
}

// round 5
// speedup vs baseline: 1.8023x; 1.4119x over previous
#include <cuda_runtime.h>
#include <cuda_bf16.h>
#include <cstdint>

#define BB 64
#define TT 2048
#define MM 512
#define PP 512

// Device scratch
__device__ float g_dsp[BB * MM];
__device__ float g_part[8 * BB * MM];            // dsproj k-slab partials
__device__ __nv_bfloat16 g_UT[MM * MM];          // U_d^T [n][k], bf16
__device__ float g_l[BB * TT];
__device__ int g_dummy;

__device__ __forceinline__ float tanh_fast(float x) {
    float y;
    asm("tanh.approx.f32 %0, %1;" : "=f"(y) : "f"(x));
    return y;
}
__device__ __forceinline__ void cp_async16(uint32_t dst, const void* src) {
    asm volatile("cp.async.cg.shared.global [%0], [%1], 16;" :: "r"(dst), "l"(src) : "memory");
}
__device__ __forceinline__ void cp_commit() {
    asm volatile("cp.async.commit_group;" ::: "memory");
}
__device__ __forceinline__ void cp_wait1() {
    asm volatile("cp.async.wait_group 1;" ::: "memory");
}

#define SWZ16(r, c) (((r) << 10) + (((c) ^ ((r) & 7)) << 4))

// ---------------------------------------------------------------------------
// Kernel 0: dummy (keeps ncu capture slot on k_main)
// ---------------------------------------------------------------------------
__global__ void k_dummy() { if (threadIdx.x == 0) g_dummy = 1; }

// ---------------------------------------------------------------------------
// Kernel 1a: dsproj partials. grid = 16 bgrp x 8 kslab = 128 CTAs, 512 thr.
// Thread = one n column; 4 batch accumulators; k-slab of 128.
// ---------------------------------------------------------------------------
__global__ __launch_bounds__(512) void k_dsproj1(const float* __restrict__ h,
                                                 const float* __restrict__ c,
                                                 const float* __restrict__ W) {
    __shared__ float ds[4][128];
    int bgrp = blockIdx.x >> 3;          // 0..15 (4 batches each)
    int ks = blockIdx.x & 7;             // k-slab of 128
    int tid = threadIdx.x;               // n = tid
    // load ds slab for 4 batches
    if (tid < 512) {
        int j = tid >> 7, kk = tid & 127;
        int k = ks * 128 + kk;
        float v = (k < PP) ? h[(bgrp * 4 + j) * PP + k]
                           : c[(bgrp * 4 + j) * PP + (k - PP)];
        ds[j][kk] = v;
    }
    __syncthreads();
    float a0 = 0.f, a1 = 0.f, a2 = 0.f, a3 = 0.f;
    const float* Wp = W + (ks * 128) * MM + tid;
#pragma unroll 8
    for (int kk = 0; kk < 128; kk++) {
        float w = Wp[kk * MM];
        a0 = fmaf(w, ds[0][kk], a0);
        a1 = fmaf(w, ds[1][kk], a1);
        a2 = fmaf(w, ds[2][kk], a2);
        a3 = fmaf(w, ds[3][kk], a3);
    }
    int base = (ks * BB + bgrp * 4) * MM + tid;
    g_part[base] = a0;
    g_part[base + MM] = a1;
    g_part[base + 2 * MM] = a2;
    g_part[base + 3 * MM] = a3;
}

// ---------------------------------------------------------------------------
// Kernel 1b: reduce partials + biases. grid = 64 (b), 512 thr (n).
// ---------------------------------------------------------------------------
__global__ __launch_bounds__(512) void k_dsproj2(const float* __restrict__ bwd,
                                                 const float* __restrict__ bud) {
    int b = blockIdx.x, n = threadIdx.x;
    float s = bwd[n] + bud[n];
#pragma unroll
    for (int ks = 0; ks < 8; ks++)
        s += g_part[(ks * BB + b) * MM + n];
    g_dsp[b * MM + n] = s;
}

// ---------------------------------------------------------------------------
// Kernel 2: g_UT[n][k] = bf16(U[k][n])
// ---------------------------------------------------------------------------
__global__ void k_transU(const float* __restrict__ U) {
    __shared__ float tile[32][33];
    int n0 = blockIdx.x * 32, k0 = blockIdx.y * 32;
    for (int i = threadIdx.y; i < 32; i += 8)
        tile[i][threadIdx.x] = U[(k0 + i) * MM + n0 + threadIdx.x];
    __syncthreads();
    for (int i = threadIdx.y; i < 32; i += 8)
        g_UT[(n0 + i) * MM + (k0 + threadIdx.x)] = __float2bfloat16(tile[threadIdx.x][i]);
}

// ---------------------------------------------------------------------------
// Kernel 3: fused GEMM + tanh + v-dot via mma.sync (bf16, fp32 accum).
// CTA = 128 t-rows x N512 x K512. A (128x512 bf16) resident in SMEM.
// 4 COMPUTE warps (wid 0-3), warp tile m64 x n32 -> acc[4][4][4].
// 4 LOADER warps (wid 4-7) stream B = U^T in 8 n64-chunks, each as two
// k-half phases through disjoint halves of one 64KB buffer (cp.async).
// ---------------------------------------------------------------------------
#define A_OFF    0
#define B_OFF    131072
#define DSP_OFF  196608
#define V_OFF    198656
#define PART_OFF 200704
#define SMEM_TOTAL 201280

__global__ __launch_bounds__(256, 1) void k_main(const float* __restrict__ enc,
                                                 const float* __restrict__ vd) {
    extern __shared__ char sm[];
    uint32_t sbase = (uint32_t)__cvta_generic_to_shared(sm);
    uint32_t sA = sbase + A_OFF;
    uint32_t sB = sbase + B_OFF;
    float* dsp_s = (float*)(sm + DSP_OFF);
    float* v_s = (float*)(sm + V_OFF);
    float* part = (float*)(sm + PART_OFF);

    int blk = blockIdx.x;
    int b = blk >> 4;
    int t0 = (blk & 15) << 7;
    int tid = threadIdx.x;
    int lane = tid & 31;
    int wid = tid >> 5;
    int wm = wid & 1;                // m64 slab
    int wn = (wid >> 1) & 1;         // n32 within chunk
    int g = lane >> 2;
    int tig = lane & 3;

    const __nv_bfloat16* UT = &g_UT[0];

    // B half loader: chunk nc (n64), k-half h -> cols h*32..h*32+31 (16B units)
    auto loadBhalf = [&](int nc, int h) {
#pragma unroll
        for (int i = tid - 128; i < 2048; i += 128) {
            int r = i >> 5;                       // chunk row 0..63
            int c = i & 31;                       // 16B col within half
            cp_async16(sB + SWZ16(r, (h << 5) + c),
                       UT + ((nc << 6) + r) * MM + (h << 8) + (c << 3));
        }
    };

    // Prologue: loaders queue both halves of chunk 0 (overlap with A load)
    if (tid >= 128) {
        loadBhalf(0, 0); cp_commit();
        loadBhalf(0, 1); cp_commit();
    }

    // Load A: 128 x 512 fp32 -> bf16 swizzled (all 256 threads)
    {
        const float4* src = (const float4*)(enc + (size_t)(b * TT + t0) * MM);
#pragma unroll 8
        for (int i = tid; i < 8192; i += 256) {
            int r = i >> 6;
            int c = i & 63;
            float4 f0 = src[(r << 7) + (c << 1)];
            float4 f1 = src[(r << 7) + (c << 1) + 1];
            __nv_bfloat162 p0 = __floats2bfloat162_rn(f0.x, f0.y);
            __nv_bfloat162 p1 = __floats2bfloat162_rn(f0.z, f0.w);
            __nv_bfloat162 p2 = __floats2bfloat162_rn(f1.x, f1.y);
            __nv_bfloat162 p3 = __floats2bfloat162_rn(f1.z, f1.w);
            uint4 u;
            u.x = *(uint32_t*)&p0; u.y = *(uint32_t*)&p1;
            u.z = *(uint32_t*)&p2; u.w = *(uint32_t*)&p3;
            *(uint4*)(sm + A_OFF + SWZ16(r, c)) = u;
        }
        for (int i = tid; i < MM; i += 256) {
            dsp_s[i] = g_dsp[b * MM + i];
            v_s[i] = vd[i];
        }
    }

    // ldmatrix lane-address components (compute warps)
    int aRowB = (wm << 6) + (lane & 15);          // + mi*16
    int aCadd = (lane >> 4);
    int bQuad = lane >> 3;
    int bRowIn = lane & 7;
    int bCadd = bQuad & 1;
    int bBlkHalf = bQuad >> 1;
    int bN0 = (wn << 5) + (bBlkHalf << 3) + bRowIn;
    int bN1 = bN0 + 16;

    uint32_t af[2][4][4];
    uint32_t bfr[2][2][4];
    float acc[4][4][4];
    float lp[8] = {0.f, 0.f, 0.f, 0.f, 0.f, 0.f, 0.f, 0.f};

    auto loadFrags = [&](int buf, int ks) {
#pragma unroll
        for (int mi = 0; mi < 4; mi++) {
            uint32_t addr = sA + SWZ16(aRowB + (mi << 4), (ks << 1) + aCadd);
            asm volatile("ldmatrix.sync.aligned.m8n8.x4.shared.b16 {%0,%1,%2,%3}, [%4];"
                         : "=r"(af[buf][mi][0]), "=r"(af[buf][mi][1]),
                           "=r"(af[buf][mi][2]), "=r"(af[buf][mi][3]) : "r"(addr));
        }
#pragma unroll
        for (int jp = 0; jp < 2; jp++) {
            uint32_t addr = sB + SWZ16(jp ? bN1 : bN0, (ks << 1) + bCadd);
            asm volatile("ldmatrix.sync.aligned.m8n8.x4.shared.b16 {%0,%1,%2,%3}, [%4];"
                         : "=r"(bfr[buf][jp][0]), "=r"(bfr[buf][jp][1]),
                           "=r"(bfr[buf][jp][2]), "=r"(bfr[buf][jp][3]) : "r"(addr));
        }
    };

    for (int nc = 0; nc < 8; nc++) {
        if (tid < 128) {
#pragma unroll
            for (int mi = 0; mi < 4; mi++)
#pragma unroll
                for (int j = 0; j < 4; j++)
#pragma unroll
                    for (int q = 0; q < 4; q++) acc[mi][j][q] = 0.f;
        }

#pragma unroll
        for (int h = 0; h < 2; h++) {
            if (tid >= 128) cp_wait1();
            __syncthreads();                 // B half (nc,h) ready; A ready (first)

            if (tid < 128) {
                int kbase = h << 4;
                loadFrags(0, kbase);
#pragma unroll
                for (int kk = 0; kk < 16; kk++) {
                    int cur = kk & 1;
                    if (kk < 15) loadFrags(cur ^ 1, kbase + kk + 1);
#pragma unroll
                    for (int mi = 0; mi < 4; mi++)
#pragma unroll
                        for (int jp = 0; jp < 2; jp++) {
                            asm volatile("mma.sync.aligned.m16n8k16.row.col.f32.bf16.bf16.f32 "
                                "{%0,%1,%2,%3}, {%4,%5,%6,%7}, {%8,%9}, {%0,%1,%2,%3};"
                                : "+f"(acc[mi][jp * 2][0]), "+f"(acc[mi][jp * 2][1]),
                                  "+f"(acc[mi][jp * 2][2]), "+f"(acc[mi][jp * 2][3])
                                : "r"(af[cur][mi][0]), "r"(af[cur][mi][1]),
                                  "r"(af[cur][mi][2]), "r"(af[cur][mi][3]),
                                  "r"(bfr[cur][jp][0]), "r"(bfr[cur][jp][1]));
                            asm volatile("mma.sync.aligned.m16n8k16.row.col.f32.bf16.bf16.f32 "
                                "{%0,%1,%2,%3}, {%4,%5,%6,%7}, {%8,%9}, {%0,%1,%2,%3};"
                                : "+f"(acc[mi][jp * 2 + 1][0]), "+f"(acc[mi][jp * 2 + 1][1]),
                                  "+f"(acc[mi][jp * 2 + 1][2]), "+f"(acc[mi][jp * 2 + 1][3])
                                : "r"(af[cur][mi][0]), "r"(af[cur][mi][1]),
                                  "r"(af[cur][mi][2]), "r"(af[cur][mi][3]),
                                  "r"(bfr[cur][jp][2]), "r"(bfr[cur][jp][3]));
                        }
                }
            }
            __syncthreads();                 // half (nc,h) fully consumed

            if (tid >= 128) {
                int ph = (nc << 1) + h;
                if (ph < 14) loadBhalf((ph + 2) >> 1, (ph + 2) & 1);
                cp_commit();
            }
        }

        // Epilogue for chunk nc (compute warps only, overlaps B loads)
        if (tid < 128) {
            int nbase = (nc << 6) + (wn << 5) + (tig << 1);
#pragma unroll
            for (int mi = 0; mi < 4; mi++)
#pragma unroll
                for (int j = 0; j < 4; j++) {
                    int cb = nbase + (j << 3);
                    float v0 = v_s[cb], v1 = v_s[cb + 1];
                    float d0 = dsp_s[cb], d1 = dsp_s[cb + 1];
                    lp[mi * 2 + 0] += v0 * tanh_fast(acc[mi][j][0] + d0)
                                    + v1 * tanh_fast(acc[mi][j][1] + d1);
                    lp[mi * 2 + 1] += v0 * tanh_fast(acc[mi][j][2] + d0)
                                    + v1 * tanh_fast(acc[mi][j][3] + d1);
                }
        }
    }

    // Reduce over quad lanes (cols), then over wn pair via smem
    if (tid < 128) {
#pragma unroll
        for (int q = 0; q < 8; q++) {
            lp[q] += __shfl_xor_sync(0xffffffffu, lp[q], 1);
            lp[q] += __shfl_xor_sync(0xffffffffu, lp[q], 2);
        }
        if (wn == 1 && tig == 0) {
#pragma unroll
            for (int mi = 0; mi < 4; mi++)
#pragma unroll
                for (int s = 0; s < 2; s++)
                    part[(wm << 6) + (mi << 4) + (s << 3) + g] = lp[mi * 2 + s];
        }
    }
    __syncthreads();
    if (tid < 128 && wn == 0 && tig == 0) {
#pragma unroll
        for (int mi = 0; mi < 4; mi++)
#pragma unroll
            for (int s = 0; s < 2; s++) {
                int r = (wm << 6) + (mi << 4) + (s << 3) + g;
                g_l[b * TT + t0 + r] = lp[mi * 2 + s] + part[r];
            }
    }
}

// ---------------------------------------------------------------------------
// Kernel 4: softmax over T per batch
// ---------------------------------------------------------------------------
__global__ void k_softmax(float* __restrict__ out) {
    __shared__ float red[8];
    int b = blockIdx.x, tid = threadIdx.x, lane = tid & 31, wid = tid >> 5;
    float vals[8];
    float m = -1e30f;
#pragma unroll
    for (int i = 0; i < 8; i++) {
        vals[i] = g_l[b * TT + i * 256 + tid];
        m = fmaxf(m, vals[i]);
    }
#pragma unroll
    for (int o = 16; o; o >>= 1) m = fmaxf(m, __shfl_xor_sync(0xffffffffu, m, o));
    if (lane == 0) red[wid] = m;
    __syncthreads();
    m = red[0];
#pragma unroll
    for (int i = 1; i < 8; i++) m = fmaxf(m, red[i]);
    __syncthreads();
    float s = 0.f;
#pragma unroll
    for (int i = 0; i < 8; i++) {
        vals[i] = __expf(vals[i] - m);
        s += vals[i];
    }
#pragma unroll
    for (int o = 16; o; o >>= 1) s += __shfl_xor_sync(0xffffffffu, s, o);
    if (lane == 0) red[wid] = s;
    __syncthreads();
    s = 0.f;
#pragma unroll
    for (int i = 0; i < 8; i++) s += red[i];
    float inv = 1.0f / s;
#pragma unroll
    for (int i = 0; i < 8; i++) out[b * TT + i * 256 + tid] = vals[i] * inv;
}

// ---------------------------------------------------------------------------
extern "C" void kernel_launch(void* const* d_in, const int* in_sizes, int n_in,
                              void* d_out, int out_size) {
    const float* h   = (const float*)d_in[0];
    const float* c   = (const float*)d_in[1];
    const float* enc = (const float*)d_in[2];
    const float* W   = (const float*)d_in[3];
    const float* bwd = (const float*)d_in[4];
    const float* U   = (const float*)d_in[5];
    const float* bud = (const float*)d_in[6];
    const float* vd  = (const float*)d_in[7];
    float* out = (float*)d_out;

    cudaFuncSetAttribute(k_main, cudaFuncAttributeMaxDynamicSharedMemorySize, SMEM_TOTAL);

    k_dummy<<<1, 32>>>();
    k_dsproj1<<<128, 512>>>(h, c, W);
    k_dsproj2<<<64, 512>>>(bwd, bud);
    k_transU<<<dim3(16, 16), dim3(32, 8)>>>(U);
    k_main<<<(BB * TT) / 128, 256, SMEM_TOTAL>>>(enc, vd);
    k_softmax<<<BB, 256>>>(out);
}